// round 1
// baseline (speedup 1.0000x reference)
#include <cuda_runtime.h>
#include <stdint.h>

// ArnoldCat, 7 iterations, n = 1024.
// One iteration: out[a,b] = in[(a+b)%n, (2a+b)%n]  (src = M (a,b), M=[[1,1],[2,1]])
// Seven iterations compose: src = M^7 (a,b) mod 1024, M^7 = [[239,169],[338,239]].
// => out[B,a,b,c] = in[B, (239a+169b)&1023, (338a+239b)&1023, c]
//
// Layout (16,1024,1024,3) f32 row-major:
//   linear = ((B*1024 + y)*1024 + x)*3 + c
//
// One thread per output float (3 per pixel): writes are perfectly coalesced
// (warp = 128 contiguous bytes). Reads gather 12B pixels; the 3 lanes of a
// pixel coalesce into its 1-2 sectors. Per-batch input image is 12.6 MB and
// lives in L2, so DRAM reads stay ~1x despite the scatter. Streaming stores
// (st.global.cs) keep writes from evicting the resident input.

static constexpr unsigned N_FLOATS = 16u * 1024u * 1024u * 3u;  // 50331648
static constexpr unsigned THREADS  = 256u;
static constexpr unsigned BLOCKS   = N_FLOATS / THREADS;        // 196608, exact

__global__ void __launch_bounds__(THREADS)
arnold_cat7_kernel(const float* __restrict__ in, float* __restrict__ out) {
    unsigned idx = blockIdx.x * THREADS + threadIdx.x;

    unsigned p = idx / 3u;          // pixel index (mul-high, cheap)
    unsigned c = idx - p * 3u;      // channel 0..2

    unsigned b     = p & 1023u;          // output col
    unsigned a     = (p >> 10) & 1023u;  // output row
    unsigned batch = p >> 20;            // 0..15

    unsigned sr = (239u * a + 169u * b) & 1023u;
    unsigned sc = (338u * a + 239u * b) & 1023u;

    unsigned src = batch * 3145728u + sr * 3072u + sc * 3u + c;

    float v = __ldg(in + src);
    __stcs(out + idx, v);
}

extern "C" void kernel_launch(void* const* d_in, const int* in_sizes, int n_in,
                              void* d_out, int out_size) {
    (void)in_sizes; (void)n_in; (void)out_size;
    const float* in = (const float*)d_in[0];
    float* out = (float*)d_out;
    arnold_cat7_kernel<<<BLOCKS, THREADS>>>(in, out);
}

// round 2
// speedup vs baseline: 1.2685x; 1.2685x over previous
#include <cuda_runtime.h>
#include <stdint.h>

// ArnoldCat, 7 iterations, n = 1024, collapsed to a single affine gather:
//   M = [[1,1],[2,1]],  M^7 mod 1024 = [[239,169],[338,239]]
//   out[B,a,b,c] = in[B, (239a+169b)&1023, (338a+239b)&1023, c]
//
// Round-1 result: 137.7us, latency-bound (all pipes < 60%, issue 26%).
// Fix: 8 independent elements per thread (block-strided) -> MLP=8 per
// thread, loads issued before any store. Warp-level access pattern is
// unchanged: every LDG/STG instruction touches 32 consecutive floats
// (coalesced stores, ~1.37 sectors/pixel gather reads).
// Block footprint is a contiguous 8KB output slab, so batches are swept
// sequentially and the 12.6MB per-batch input image stays L2-resident.

static constexpr unsigned N_FLOATS = 16u * 1024u * 1024u * 3u;  // 50331648
static constexpr unsigned THREADS  = 256u;
static constexpr unsigned PER_THD  = 8u;
static constexpr unsigned PER_BLK  = THREADS * PER_THD;          // 2048
static constexpr unsigned BLOCKS   = N_FLOATS / PER_BLK;         // 24576, exact

__global__ void __launch_bounds__(THREADS)
arnold_cat7_kernel(const float* __restrict__ in, float* __restrict__ out) {
    unsigned base = blockIdx.x * PER_BLK + threadIdx.x;

    unsigned src[PER_THD];
    #pragma unroll
    for (unsigned i = 0; i < PER_THD; ++i) {
        unsigned idx = base + i * THREADS;

        unsigned p = idx / 3u;          // pixel index
        unsigned c = idx - p * 3u;      // channel 0..2

        unsigned b     = p & 1023u;          // output col
        unsigned a     = (p >> 10) & 1023u;  // output row
        unsigned batch = p >> 20;            // 0..15

        unsigned sr = (239u * a + 169u * b) & 1023u;
        unsigned sc = (338u * a + 239u * b) & 1023u;

        src[i] = batch * 3145728u + sr * 3072u + sc * 3u + c;
    }

    float v[PER_THD];
    #pragma unroll
    for (unsigned i = 0; i < PER_THD; ++i)      // 8 independent LDGs, MLP=8
        v[i] = __ldg(in + src[i]);

    #pragma unroll
    for (unsigned i = 0; i < PER_THD; ++i)      // coalesced streaming stores
        __stcs(out + base + i * THREADS, v[i]);
}

extern "C" void kernel_launch(void* const* d_in, const int* in_sizes, int n_in,
                              void* d_out, int out_size) {
    (void)in_sizes; (void)n_in; (void)out_size;
    const float* in = (const float*)d_in[0];
    float* out = (float*)d_out;
    arnold_cat7_kernel<<<BLOCKS, THREADS>>>(in, out);
}

// round 3
// speedup vs baseline: 2.1661x; 1.7076x over previous
#include <cuda_runtime.h>

// ArnoldCat ^7, n=1024. Single affine gather: out[a,b] <- in[239a+169b, 338a+239b] (mod 1024).
//
// Lattice re-blocking: (a,b) = (169k', j' - 239k') mod 1024 is a bijection in (k',j').
// Then source(a,b) = (169j', k' + 239j').
// Tile (m,n): k' = 32m+k, j' = 32n+j, k,j in [0,32).
//   read  (fixed j): src row 169j', 32 consecutive cols (32m + 239j') + k   -> 384B coalesced
//   write (fixed k): out row 169k', 32 consecutive cols (32n - 239k') + j   -> 384B coalesced
// SMEM transpose between the two orderings, row stride 99 floats (conflict-free both phases).
// Tiles partition both input and output exactly -> every DRAM sector touched once per direction.

static constexpr unsigned STRIDE     = 99u;                // smem floats per j-row (96 + pad)
static constexpr unsigned IMG_FLOATS = 1024u * 3072u;      // per-batch image
static constexpr unsigned THREADS    = 256u;
static constexpr unsigned BLOCKS     = 16u * 32u * 32u;    // batch x m x n = 16384

__global__ void __launch_bounds__(THREADS)
arnold_tile_kernel(const float* __restrict__ in, float* __restrict__ out) {
    __shared__ float tile[32u * STRIDE];                   // 12672 B

    unsigned id    = blockIdx.x;
    unsigned n     = id & 31u;
    unsigned m     = (id >> 5) & 31u;
    unsigned batch = id >> 10;

    unsigned lane = threadIdx.x & 31u;
    unsigned warp = threadIdx.x >> 5;

    const float* inb  = in  + batch * IMG_FLOATS;
    float*       outb = out + batch * IMG_FLOATS;

    // ---- Phase 1: gather 32 contiguous 384B source segments into SMEM ----
    #pragma unroll
    for (unsigned it = 0; it < 4; ++it) {
        unsigned j   = warp + 8u * it;                     // j in [0,32)
        unsigned jp  = 32u * n + j;                        // j'
        unsigned ry  = (169u * jp) & 1023u;                // source row
        unsigned cb3 = ((32u * m + 239u * jp) & 1023u) * 3u;  // source col base (floats)
        const float* rowp = inb + ry * 3072u;
        #pragma unroll
        for (unsigned t = 0; t < 3; ++t) {
            unsigned f = lane + 32u * t;                   // float within 96-float segment
            unsigned o = cb3 + f;
            if (o >= 3072u) o -= 3072u;                    // rare row wrap
            tile[j * STRIDE + f] = __ldcs(rowp + o);       // stream: zero reuse
        }
    }
    __syncthreads();

    // ---- Phase 2: scatter 32 contiguous 384B output segments from SMEM ----
    #pragma unroll
    for (unsigned it = 0; it < 4; ++it) {
        unsigned k   = warp + 8u * it;                     // k in [0,32)
        unsigned kp  = 32u * m + k;                        // k'
        unsigned a   = (169u * kp) & 1023u;                // output row
        unsigned ob3 = ((32u * n - 239u * kp) & 1023u) * 3u;  // output col base (floats)
        float* rowp = outb + a * 3072u;
        #pragma unroll
        for (unsigned t = 0; t < 3; ++t) {
            unsigned g = lane + 32u * t;
            unsigned o = ob3 + g;
            if (o >= 3072u) o -= 3072u;                    // rare row wrap
            // output float g -> tile pixel j = g/3, channel c = g%3, element [j][3k+c]
            __stcs(rowp + o, tile[(g / 3u) * STRIDE + 3u * k + (g % 3u)]);
        }
    }
}

extern "C" void kernel_launch(void* const* d_in, const int* in_sizes, int n_in,
                              void* d_out, int out_size) {
    (void)in_sizes; (void)n_in; (void)out_size;
    arnold_tile_kernel<<<BLOCKS, THREADS>>>((const float*)d_in[0], (float*)d_out);
}